// round 4
// baseline (speedup 1.0000x reference)
#include <cuda_runtime.h>
#include <math.h>
#include <float.h>

// Problem dims
#define LL 64
#define BB 128
#define EE 512
#define HH 256
#define H4 1024
#define DD 512      // 2H
#define NG 2048     // fused gate dim (both directions)
#define NROWS 16384 // 2 sentences * L * B

typedef unsigned long long ull;

// f32x2 packed helpers (exact fp32, 2x fma-pipe throughput)
#define FMA2(d, a, b) asm("fma.rn.f32x2 %0, %1, %2, %0;" : "+l"(d) : "l"(a), "l"(b))
#define PACK2(d, lo, hi) asm("mov.b64 %0, {%1, %2};" : "=l"(d) : "f"(lo), "f"(hi))
#define DUP2(d, x) asm("mov.b64 %0, {%1, %1};" : "=l"(d) : "f"(x))
#define UNPACK2(lo, hi, v) asm("mov.b64 {%0, %1}, %2;" : "=f"(lo), "=f"(hi) : "l"(v))

__device__ __forceinline__ float tanh_fast(float x) {
    float y;
    asm("tanh.approx.f32 %0, %1;" : "=f"(y) : "f"(x));
    return y;
}
__device__ __forceinline__ float sig_fast(float x) {
    return fmaf(0.5f, tanh_fast(0.5f * x), 0.5f);
}

// ---------------- scratch (device globals; no allocation allowed) ----------
__device__ float g_x[2 * LL * BB * EE];          // embedded inputs  (33.5 MB)
__device__ float g_xg[(size_t)2 * LL * BB * NG]; // input-gate GEMM out (134 MB)
__device__ float g_o[2 * LL * BB * DD];          // o1, o2 outputs (L,B,D) (33.5 MB)
__device__ float g_h[2 * 4 * BB * HH];           // double-buffered h state (1 MB)
__device__ float g_mp1[BB * DD];
__device__ float g_attsm[BB * LL];
__device__ unsigned g_sync;
__device__ unsigned g_done;

// ---------------- kernel 0: zero h state ----------------
__global__ void zero_h_kernel() {
    int i = blockIdx.x * blockDim.x + threadIdx.x;
    if (i < 2 * 4 * BB * HH) g_h[i] = 0.0f;
}

// ---------------- kernel 1: embedding gather ----------------
__global__ void gather_kernel(const int* __restrict__ t1, const int* __restrict__ t2,
                              const float* __restrict__ emb) {
    int row = blockIdx.x;            // 0..16383
    int s   = row >> 13;
    int r   = row & 8191;
    int tok = s ? t2[r] : t1[r];
    const float4* src = (const float4*)(emb + (size_t)tok * EE);
    float4* dst = (float4*)(g_x + (size_t)row * EE);
    int tid = threadIdx.x;           // 128 threads, 128 float4 per row
    dst[tid] = src[tid];
}

// ---------------- kernel 2: input projection GEMM (f32x2 packed) ----------
// C[row][n] = sum_k g_x[row][k] * W[n][k] + bias[n]
// BM=128, BN=128, BK=16, 256 threads, thread tile 8x8 packed along M.
__global__ __launch_bounds__(256) void gemm_kernel(
    const float* __restrict__ Wf, const float* __restrict__ Wb,
    const float* __restrict__ bihf, const float* __restrict__ bhhf,
    const float* __restrict__ bihb, const float* __restrict__ bhhb) {
    __shared__ float As[16][132];   // [k][row]
    __shared__ float Bs[16][132];   // [k][col]

    int bm = blockIdx.x;             // 0..127  (M tiles)
    int bn = blockIdx.y;             // 0..15   (N tiles of 128)
    int n0 = bn * 128;
    int dirb = (n0 >= 1024) ? 1 : 0;
    const float* W = dirb ? Wb : Wf;
    int nW0 = dirb ? (n0 - 1024) : n0;

    const float* A = g_x + (size_t)bm * 128 * EE;
    int tid = threadIdx.x;
    int tr = tid >> 4;               // 0..15 -> rows r0..r0+7 (4 packed pairs)
    int tc = tid & 15;               // 0..15 -> cols c0..c0+7
    int r0 = tr * 8, c0 = tc * 8;

    ull acc2[4][8];
#pragma unroll
    for (int p = 0; p < 4; p++)
#pragma unroll
        for (int c = 0; c < 8; c++) acc2[p][c] = 0ULL;

    for (int k0 = 0; k0 < EE; k0 += 16) {
        // A tile (128 x 16) -> As[k][row]
#pragma unroll
        for (int i = 0; i < 2; i++) {
            int idx = tid + 256 * i;     // 512 float4
            int ar = idx >> 2, k4 = idx & 3;
            float4 v = *(const float4*)(A + (size_t)ar * EE + k0 + k4 * 4);
            As[k4 * 4 + 0][ar] = v.x; As[k4 * 4 + 1][ar] = v.y;
            As[k4 * 4 + 2][ar] = v.z; As[k4 * 4 + 3][ar] = v.w;
        }
        // W tile (128 x 16) -> Bs[k][col]
#pragma unroll
        for (int i = 0; i < 2; i++) {
            int idx = tid + 256 * i;
            int nr = idx >> 2, k4 = idx & 3;
            float4 v = *(const float4*)(W + (size_t)(nW0 + nr) * EE + k0 + k4 * 4);
            Bs[k4 * 4 + 0][nr] = v.x; Bs[k4 * 4 + 1][nr] = v.y;
            Bs[k4 * 4 + 2][nr] = v.z; Bs[k4 * 4 + 3][nr] = v.w;
        }
        __syncthreads();
#pragma unroll
        for (int kk = 0; kk < 16; kk++) {
            // 8 rows = 4 packed pairs (rows adjacent in As -> pairs come free)
            ull apair[4];
            {
                ulonglong2 a0 = *(const ulonglong2*)&As[kk][r0];
                ulonglong2 a1 = *(const ulonglong2*)&As[kk][r0 + 4];
                apair[0] = a0.x; apair[1] = a0.y; apair[2] = a1.x; apair[3] = a1.y;
            }
            // 8 cols -> duplicated packs
            float4 bv0 = *(const float4*)&Bs[kk][c0];
            float4 bv1 = *(const float4*)&Bs[kk][c0 + 4];
            ull bd[8];
            DUP2(bd[0], bv0.x); DUP2(bd[1], bv0.y); DUP2(bd[2], bv0.z); DUP2(bd[3], bv0.w);
            DUP2(bd[4], bv1.x); DUP2(bd[5], bv1.y); DUP2(bd[6], bv1.z); DUP2(bd[7], bv1.w);
#pragma unroll
            for (int p = 0; p < 4; p++)
#pragma unroll
                for (int c = 0; c < 8; c++)
                    FMA2(acc2[p][c], apair[p], bd[c]);
        }
        __syncthreads();
    }

    // bias + store (rows r0+2p, r0+2p+1; cols c0..c0+7)
    float bs[8];
#pragma unroll
    for (int c = 0; c < 8; c++) {
        int n = n0 + c0 + c;
        bs[c] = dirb ? (bihb[n - 1024] + bhhb[n - 1024]) : (bihf[n] + bhhf[n]);
    }
#pragma unroll
    for (int p = 0; p < 4; p++) {
        float lo[8], hi[8];
#pragma unroll
        for (int c = 0; c < 8; c++) {
            UNPACK2(lo[c], hi[c], acc2[p][c]);
            lo[c] += bs[c]; hi[c] += bs[c];
        }
        size_t row_lo = (size_t)(bm * 128 + r0 + 2 * p) * NG + n0 + c0;
        size_t row_hi = row_lo + NG;
        *(float4*)(g_xg + row_lo)     = make_float4(lo[0], lo[1], lo[2], lo[3]);
        *(float4*)(g_xg + row_lo + 4) = make_float4(lo[4], lo[5], lo[6], lo[7]);
        *(float4*)(g_xg + row_hi)     = make_float4(hi[0], hi[1], hi[2], hi[3]);
        *(float4*)(g_xg + row_hi + 4) = make_float4(hi[4], hi[5], hi[6], hi[7]);
    }
}

// ---------------- kernel 3: persistent LSTM recurrence (f32x2, gate-packed) -
// 128 blocks = 4 scans x 32 hidden-slices. 128 threads/block.
// Thread (ct = unit 0..7, bt = 0..15): 8 batches (b = bt + 16*bi) x 4 gates.
// Accumulators packed along gates: acc2[bi][0]=(i,f), acc2[bi][1]=(g,o).
// Whh pre-interleaved in smem as float4 (wi,wf,wg,wo)[k] -> packed pairs free.
#define WST 1028                     // sh_w unit stride (bank-spread)
#define HST 260                      // sh_h batch stride

__global__ __launch_bounds__(128, 1) void lstm_kernel(const float* __restrict__ Whh_f,
                                                      const float* __restrict__ Whh_b) {
    extern __shared__ float sm[];
    float* sh_w = sm;                     // [8 units][1028] -> (k*4+g)
    float* sh_h = sm + 8 * WST;           // [128 batches][260]

    const int tid = threadIdx.x;
    const int rec = blockIdx.x >> 5;      // (s1,f)(s1,b)(s2,f)(s2,b)
    const int slice = blockIdx.x & 31;
    const int s = rec >> 1;
    const int dir = rec & 1;
    const int ct = tid & 7;               // unit within slice
    const int bt = tid >> 3;              // 0..15
    const int j = slice * 8 + ct;         // hidden unit 0..255
    const float* Whh = dir ? Whh_b : Whh_f;

    // Build interleaved weights: sh_w[jj*WST + k*4 + g] = Whh[g*256+slice*8+jj][k]
    for (int idx = tid; idx < 32 * 64; idx += 128) {
        int cl = idx >> 6;                // 0..31 : (g, jj)
        int k4 = idx & 63;
        int g = cl >> 3, jj = cl & 7;
        float4 v = *(const float4*)(Whh + (size_t)(g * 256 + slice * 8 + jj) * HH + k4 * 4);
        float* wp = sh_w + jj * WST + k4 * 16 + g;
        wp[0] = v.x; wp[4] = v.y; wp[8] = v.z; wp[12] = v.w;
    }

    const float* wbase = sh_w + ct * WST;
    float c_st[8];
#pragma unroll
    for (int bi = 0; bi < 8; bi++) c_st[bi] = 0.0f;

    for (int t = 0; t < 64; ++t) {
        const int l = dir ? (63 - t) : t;

        // prefetch xg (independent of the barrier)
        const float* xgp = g_xg + ((size_t)(s * 8192 + l * 128)) * NG + dir * 1024 + j;
        float xv[8][4];
#pragma unroll
        for (int bi = 0; bi < 8; bi++) {
            const float* xr = xgp + (size_t)(bt + 16 * bi) * NG;
            xv[bi][0] = __ldcg(xr);
            xv[bi][1] = __ldcg(xr + 256);
            xv[bi][2] = __ldcg(xr + 512);
            xv[bi][3] = __ldcg(xr + 768);
        }

        // stage h_prev into smem (L2-only: L1 stale across global barrier)
        const float* hsrc = g_h + (size_t)((t & 1) * 4 + rec) * BB * HH;
#pragma unroll 4
        for (int it = 0; it < 64; it++) {
            int idx = tid + 128 * it;
            int b = idx >> 6, k4 = idx & 63;
            float4 v = __ldcg((const float4*)(hsrc + (size_t)b * HH + k4 * 4));
            *(float4*)(sh_h + b * HST + k4 * 4) = v;
        }

        // init acc with xg: (i,f) and (g,o) packs
        ull acc2[8][2];
#pragma unroll
        for (int bi = 0; bi < 8; bi++) {
            PACK2(acc2[bi][0], xv[bi][0], xv[bi][1]);
            PACK2(acc2[bi][1], xv[bi][2], xv[bi][3]);
        }
        __syncthreads();

        // gates += h_prev @ Whh^T
#pragma unroll 4
        for (int k4 = 0; k4 < 64; ++k4) {
            float4 hv[8];
#pragma unroll
            for (int bi = 0; bi < 8; bi++)
                hv[bi] = *(const float4*)(sh_h + (bt + 16 * bi) * HST + k4 * 4);
#pragma unroll
            for (int i = 0; i < 4; i++) {
                ulonglong2 wv = *(const ulonglong2*)(wbase + (k4 * 4 + i) * 4);
#pragma unroll
                for (int bi = 0; bi < 8; bi++) {
                    float hs = (i == 0) ? hv[bi].x : (i == 1) ? hv[bi].y
                             : (i == 2) ? hv[bi].z : hv[bi].w;
                    ull hd;
                    DUP2(hd, hs);
                    FMA2(acc2[bi][0], hd, wv.x);
                    FMA2(acc2[bi][1], hd, wv.y);
                }
            }
        }

        // nonlinearity + state update + writes
        float* hdst = g_h + (size_t)(((t + 1) & 1) * 4 + rec) * BB * HH;
        float* odst = g_o + (size_t)s * LL * BB * DD + (size_t)l * BB * DD + dir * HH + j;
#pragma unroll
        for (int bi = 0; bi < 8; bi++) {
            int b = bt + 16 * bi;
            float pi, pf, pg, po;
            UNPACK2(pi, pf, acc2[bi][0]);
            UNPACK2(pg, po, acc2[bi][1]);
            float ig = sig_fast(pi);
            float fg = sig_fast(pf);
            float gg = tanh_fast(pg);
            float og = sig_fast(po);
            float c = fmaf(fg, c_st[bi], ig * gg);
            c_st[bi] = c;
            float h = og * tanh_fast(c);
            hdst[(size_t)b * HH + j] = h;
            odst[(size_t)b * DD] = h;
        }

        // global barrier (all 128 blocks co-resident at 1/SM)
        __syncthreads();   // all threads' stores issued before arrival
        if (tid == 0) {
            __threadfence();
            atomicAdd(&g_sync, 1u);
            unsigned target = 128u * (unsigned)(t + 1);
            while (*((volatile unsigned*)&g_sync) < target) { }
            __threadfence();
        }
        __syncthreads();
    }

    // self-reset for graph replays
    if (tid == 0) {
        unsigned old = atomicAdd(&g_done, 1u);
        if (old == 127u) {
            g_done = 0u;
            g_sync = 0u;
            __threadfence();
        }
    }
}

// ---------------- kernel 4: mp1 = max over time of o1 ----------------
__global__ void mp1_kernel() {
    int b = blockIdx.x;
    for (int d = threadIdx.x; d < DD; d += blockDim.x) {
        float m = -FLT_MAX;
#pragma unroll 8
        for (int l = 0; l < LL; l++)
            m = fmaxf(m, g_o[(size_t)l * BB * DD + b * DD + d]);
        g_mp1[b * DD + d] = m;
    }
}

// ---------------- kernel 5: attention + softmax (raw-reshape semantics) ----
__global__ void att_kernel() {
    __shared__ float smp[DD];
    __shared__ float sat[LL];
    int b = blockIdx.x, l = threadIdx.x;   // 64 threads
    const float* o2 = g_o + (size_t)LL * BB * DD;
    for (int d = l; d < DD; d += LL) smp[d] = g_mp1[b * DD + d];
    __syncthreads();
    float a = 0.0f;
    for (int d = 0; d < DD; d++)
        a = fmaf(smp[d], o2[(size_t)b * DD * LL + d * LL + l], a);
    sat[l] = a;
    __syncthreads();
    float mx = -FLT_MAX;
    for (int i = 0; i < LL; i++) mx = fmaxf(mx, sat[i]);
    float ssum = 0.0f;
    for (int i = 0; i < LL; i++) ssum += expf(sat[i] - mx);
    g_attsm[b * LL + l] = expf(a - mx) / ssum;
}

// ---------------- kernel 6: new_pool + sim (fused) ----------------
__global__ void sim_kernel(float* __restrict__ out) {
    __shared__ float sal[LL];
    __shared__ float red[256];
    int b = blockIdx.x, tid = threadIdx.x;
    if (tid < LL) sal[tid] = g_attsm[b * LL + tid];
    __syncthreads();
    const float* o2 = g_o + (size_t)LL * BB * DD;
    float local = 0.0f;
    for (int d = tid; d < DD; d += 256) {
        float np = 0.0f;
#pragma unroll 8
        for (int l = 0; l < LL; l++)
            np = fmaf(sal[l], o2[(size_t)b * LL * DD + l * DD + d], np);
        local += fabsf(g_mp1[b * DD + d] - np);
    }
    red[tid] = local;
    __syncthreads();
    for (int s2 = 128; s2 > 0; s2 >>= 1) {
        if (tid < s2) red[tid] += red[tid + s2];
        __syncthreads();
    }
    if (tid == 0) out[b] = expf(-red[0]);
}

// ---------------- kernel 7: commonWords + e1h/e2h ----------------
__global__ void e_kernel(const int* __restrict__ t1, const int* __restrict__ t2,
                         float* __restrict__ out) {
    __shared__ int s1[LL];
    __shared__ int spos[LL];
    __shared__ int smask[LL];
    __shared__ int shas;
    int b = blockIdx.x, tid = threadIdx.x;
    if (tid == 0) shas = 0;
    if (tid < LL) s1[tid] = t1[tid * BB + b];
    __syncthreads();
    if (tid < LL) {
        int tok2 = t2[tid * BB + b];
        int d = -1;
        for (int jj = 0; jj < LL; jj++)
            if (s1[jj] == tok2) d = jj;
        int m = (d > 1) && (tok2 > 0);
        smask[tid] = m;
        spos[tid] = min(max(d, 0), LL - 1);
        if (m) atomicOr(&shas, 1);
    }
    __syncthreads();
    int has = shas;
    const float* o1 = g_o;
    const float* o2 = g_o + (size_t)LL * BB * DD;
    for (int d = tid; d < DD; d += 256) {
        float m1 = -FLT_MAX, m2 = -FLT_MAX;
        for (int i = 0; i < LL; i++) {
            if (smask[i]) {
                m1 = fmaxf(m1, o1[(size_t)spos[i] * BB * DD + b * DD + d]);
                m2 = fmaxf(m2, o2[(size_t)i * BB * DD + b * DD + d]);
            }
        }
        out[128 + b * DD + d] = has ? m1 : 0.0f;
        out[128 + BB * DD + b * DD + d] = has ? m2 : 0.0f;
    }
}

// ---------------- launch ----------------
extern "C" void kernel_launch(void* const* d_in, const int* in_sizes, int n_in,
                              void* d_out, int out_size) {
    const int* t1 = (const int*)d_in[0];
    const int* t2 = (const int*)d_in[1];
    const float* emb = (const float*)d_in[2];
    const float* Wihf = (const float*)d_in[3];
    const float* Whhf = (const float*)d_in[4];
    const float* bihf = (const float*)d_in[5];
    const float* bhhf = (const float*)d_in[6];
    const float* Wihb = (const float*)d_in[7];
    const float* Whhb = (const float*)d_in[8];
    const float* bihb = (const float*)d_in[9];
    const float* bhhb = (const float*)d_in[10];
    float* out = (float*)d_out;

    zero_h_kernel<<<(2 * 4 * BB * HH + 255) / 256, 256>>>();
    gather_kernel<<<NROWS, 128>>>(t1, t2, emb);

    dim3 ggrid(128, 16);
    gemm_kernel<<<ggrid, 256>>>(Wihf, Wihb, bihf, bhhf, bihb, bhhb);

    const int lstm_smem = (8 * WST + 128 * HST) * 4;  // 166,016 B
    cudaFuncSetAttribute(lstm_kernel, cudaFuncAttributeMaxDynamicSharedMemorySize, lstm_smem);
    lstm_kernel<<<128, 128, lstm_smem>>>(Whhf, Whhb);

    mp1_kernel<<<BB, 128>>>();
    att_kernel<<<BB, LL>>>();
    sim_kernel<<<BB, 256>>>(out);
    e_kernel<<<BB, 256>>>(t1, t2, out);
}

// round 6
// speedup vs baseline: 1.1376x; 1.1376x over previous
#include <cuda_runtime.h>
#include <math.h>
#include <float.h>

// Problem dims
#define LL 64
#define BB 128
#define EE 512
#define HH 256
#define H4 1024
#define DD 512      // 2H
#define NG 2048     // fused gate dim (both directions)
#define NROWS 16384 // 2 sentences * L * B

typedef unsigned long long ull;

// f32x2 packed helpers (exact fp32, 2x fma-pipe throughput)
#define FMA2(d, a, b) asm("fma.rn.f32x2 %0, %1, %2, %0;" : "+l"(d) : "l"(a), "l"(b))
#define PACK2(d, lo, hi) asm("mov.b64 %0, {%1, %2};" : "=l"(d) : "f"(lo), "f"(hi))
#define DUP2(d, x) asm("mov.b64 %0, {%1, %1};" : "=l"(d) : "f"(x))
#define UNPACK2(lo, hi, v) asm("mov.b64 {%0, %1}, %2;" : "=f"(lo), "=f"(hi) : "l"(v))

__device__ __forceinline__ float tanh_fast(float x) {
    float y;
    asm("tanh.approx.f32 %0, %1;" : "=f"(y) : "f"(x));
    return y;
}
__device__ __forceinline__ float sig_fast(float x) {
    return fmaf(0.5f, tanh_fast(0.5f * x), 0.5f);
}

// ---------------- scratch (device globals; no allocation allowed) ----------
__device__ float g_x[2 * LL * BB * EE];          // embedded inputs  (33.5 MB)
__device__ float g_xg[(size_t)2 * LL * BB * NG]; // input-gate GEMM out (134 MB)
__device__ float g_o[2 * LL * BB * DD];          // o1, o2 outputs (L,B,D) (33.5 MB)
__device__ float g_h[2 * 4 * BB * HH];           // double-buffered h state (1 MB)
__device__ float g_mp1[BB * DD];
__device__ float g_attsm[BB * LL];
__device__ unsigned g_sync;
__device__ unsigned g_done;

// ---------------- kernel 0: zero h state ----------------
__global__ void zero_h_kernel() {
    int i = blockIdx.x * blockDim.x + threadIdx.x;
    if (i < 2 * 4 * BB * HH) g_h[i] = 0.0f;
}

// ---------------- kernel 1: embedding gather ----------------
__global__ void gather_kernel(const int* __restrict__ t1, const int* __restrict__ t2,
                              const float* __restrict__ emb) {
    int row = blockIdx.x;            // 0..16383
    int s   = row >> 13;
    int r   = row & 8191;
    int tok = s ? t2[r] : t1[r];
    const float4* src = (const float4*)(emb + (size_t)tok * EE);
    float4* dst = (float4*)(g_x + (size_t)row * EE);
    int tid = threadIdx.x;           // 128 threads, 128 float4 per row
    dst[tid] = src[tid];
}

// ---------------- kernel 2: input projection GEMM (f32x2 packed) ----------
// C[row][n] = sum_k g_x[row][k] * W[n][k] + bias[n]
// BM=128, BN=128, BK=16, 256 threads, thread tile 8x8 packed along M.
__global__ __launch_bounds__(256) void gemm_kernel(
    const float* __restrict__ Wf, const float* __restrict__ Wb,
    const float* __restrict__ bihf, const float* __restrict__ bhhf,
    const float* __restrict__ bihb, const float* __restrict__ bhhb) {
    __shared__ float As[16][132];   // [k][row]
    __shared__ float Bs[16][132];   // [k][col]

    int bm = blockIdx.x;             // 0..127  (M tiles)
    int bn = blockIdx.y;             // 0..15   (N tiles of 128)
    int n0 = bn * 128;
    int dirb = (n0 >= 1024) ? 1 : 0;
    const float* W = dirb ? Wb : Wf;
    int nW0 = dirb ? (n0 - 1024) : n0;

    const float* A = g_x + (size_t)bm * 128 * EE;
    int tid = threadIdx.x;
    int tr = tid >> 4;               // 0..15 -> rows r0..r0+7 (4 packed pairs)
    int tc = tid & 15;               // 0..15 -> cols c0..c0+7
    int r0 = tr * 8, c0 = tc * 8;

    ull acc2[4][8];
#pragma unroll
    for (int p = 0; p < 4; p++)
#pragma unroll
        for (int c = 0; c < 8; c++) acc2[p][c] = 0ULL;

    for (int k0 = 0; k0 < EE; k0 += 16) {
        // A tile (128 x 16) -> As[k][row]
#pragma unroll
        for (int i = 0; i < 2; i++) {
            int idx = tid + 256 * i;     // 512 float4
            int ar = idx >> 2, k4 = idx & 3;
            float4 v = *(const float4*)(A + (size_t)ar * EE + k0 + k4 * 4);
            As[k4 * 4 + 0][ar] = v.x; As[k4 * 4 + 1][ar] = v.y;
            As[k4 * 4 + 2][ar] = v.z; As[k4 * 4 + 3][ar] = v.w;
        }
        // W tile (128 x 16) -> Bs[k][col]
#pragma unroll
        for (int i = 0; i < 2; i++) {
            int idx = tid + 256 * i;
            int nr = idx >> 2, k4 = idx & 3;
            float4 v = *(const float4*)(W + (size_t)(nW0 + nr) * EE + k0 + k4 * 4);
            Bs[k4 * 4 + 0][nr] = v.x; Bs[k4 * 4 + 1][nr] = v.y;
            Bs[k4 * 4 + 2][nr] = v.z; Bs[k4 * 4 + 3][nr] = v.w;
        }
        __syncthreads();
#pragma unroll
        for (int kk = 0; kk < 16; kk++) {
            // 8 rows = 4 packed pairs (rows adjacent in As -> pairs come free)
            ull apair[4];
            {
                ulonglong2 a0 = *(const ulonglong2*)&As[kk][r0];
                ulonglong2 a1 = *(const ulonglong2*)&As[kk][r0 + 4];
                apair[0] = a0.x; apair[1] = a0.y; apair[2] = a1.x; apair[3] = a1.y;
            }
            // 8 cols -> duplicated packs
            float4 bv0 = *(const float4*)&Bs[kk][c0];
            float4 bv1 = *(const float4*)&Bs[kk][c0 + 4];
            ull bd[8];
            DUP2(bd[0], bv0.x); DUP2(bd[1], bv0.y); DUP2(bd[2], bv0.z); DUP2(bd[3], bv0.w);
            DUP2(bd[4], bv1.x); DUP2(bd[5], bv1.y); DUP2(bd[6], bv1.z); DUP2(bd[7], bv1.w);
#pragma unroll
            for (int p = 0; p < 4; p++)
#pragma unroll
                for (int c = 0; c < 8; c++)
                    FMA2(acc2[p][c], apair[p], bd[c]);
        }
        __syncthreads();
    }

    // bias + store (rows r0+2p, r0+2p+1; cols c0..c0+7)
    float bs[8];
#pragma unroll
    for (int c = 0; c < 8; c++) {
        int n = n0 + c0 + c;
        bs[c] = dirb ? (bihb[n - 1024] + bhhb[n - 1024]) : (bihf[n] + bhhf[n]);
    }
#pragma unroll
    for (int p = 0; p < 4; p++) {
        float lo[8], hi[8];
#pragma unroll
        for (int c = 0; c < 8; c++) {
            UNPACK2(lo[c], hi[c], acc2[p][c]);
            lo[c] += bs[c]; hi[c] += bs[c];
        }
        size_t row_lo = (size_t)(bm * 128 + r0 + 2 * p) * NG + n0 + c0;
        size_t row_hi = row_lo + NG;
        *(float4*)(g_xg + row_lo)     = make_float4(lo[0], lo[1], lo[2], lo[3]);
        *(float4*)(g_xg + row_lo + 4) = make_float4(lo[4], lo[5], lo[6], lo[7]);
        *(float4*)(g_xg + row_hi)     = make_float4(hi[0], hi[1], hi[2], hi[3]);
        *(float4*)(g_xg + row_hi + 4) = make_float4(hi[4], hi[5], hi[6], hi[7]);
    }
}

// ---------------- kernel 3: persistent LSTM recurrence (f32x2, gate-packed) -
// 128 blocks = 4 scans x 32 hidden-slices. 256 threads/block (2 warps/SMSP).
// Thread (ct = unit 0..7, bt = 0..31): 4 batches (b = bt + 32*bi) x 4 gates.
// Accumulators packed along gates: acc2[bi][0]=(i,f), acc2[bi][1]=(g,o).
// Whh pre-interleaved in smem as (wi,wf,wg,wo)[k] -> packed weight pairs free.
#define WST 1028                     // sh_w unit stride (bank-spread)
#define HST 260                      // sh_h batch stride

__global__ __launch_bounds__(256, 1) void lstm_kernel(const float* __restrict__ Whh_f,
                                                      const float* __restrict__ Whh_b) {
    extern __shared__ float sm[];
    float* sh_w = sm;                     // [8 units][1028] -> (k*4+g)
    float* sh_h = sm + 8 * WST;           // [128 batches][260]

    const int tid = threadIdx.x;
    const int rec = blockIdx.x >> 5;      // (s1,f)(s1,b)(s2,f)(s2,b)
    const int slice = blockIdx.x & 31;
    const int s = rec >> 1;
    const int dir = rec & 1;
    const int ct = tid & 7;               // unit within slice
    const int bt = tid >> 3;              // 0..31
    const int j = slice * 8 + ct;         // hidden unit 0..255
    const float* Whh = dir ? Whh_b : Whh_f;

    // Build interleaved weights: sh_w[jj*WST + k*4 + g] = Whh[g*256+slice*8+jj][k]
    for (int idx = tid; idx < 32 * 64; idx += 256) {
        int cl = idx >> 6;                // 0..31 : (g, jj)
        int k4 = idx & 63;
        int g = cl >> 3, jj = cl & 7;
        float4 v = *(const float4*)(Whh + (size_t)(g * 256 + slice * 8 + jj) * HH + k4 * 4);
        float* wp = sh_w + jj * WST + k4 * 16 + g;
        wp[0] = v.x; wp[4] = v.y; wp[8] = v.z; wp[12] = v.w;
    }

    const float* wbase = sh_w + ct * WST;
    float c_st[4] = {0.f, 0.f, 0.f, 0.f};

    for (int t = 0; t < 64; ++t) {
        const int l = dir ? (63 - t) : t;

        // prefetch xg (independent of the barrier)
        const float* xgp = g_xg + ((size_t)(s * 8192 + l * 128)) * NG + dir * 1024 + j;
        float xv[4][4];
#pragma unroll
        for (int bi = 0; bi < 4; bi++) {
            const float* xr = xgp + (size_t)(bt + 32 * bi) * NG;
            xv[bi][0] = __ldcg(xr);
            xv[bi][1] = __ldcg(xr + 256);
            xv[bi][2] = __ldcg(xr + 512);
            xv[bi][3] = __ldcg(xr + 768);
        }

        // stage h_prev into smem (L2-only: L1 stale across global barrier)
        const float* hsrc = g_h + (size_t)((t & 1) * 4 + rec) * BB * HH;
#pragma unroll 8
        for (int it = 0; it < 32; it++) {
            int idx = tid + 256 * it;
            int b = idx >> 6, k4 = idx & 63;
            float4 v = __ldcg((const float4*)(hsrc + (size_t)b * HH + k4 * 4));
            *(float4*)(sh_h + b * HST + k4 * 4) = v;
        }

        // init acc with xg: (i,f) and (g,o) packs
        ull acc2[4][2];
#pragma unroll
        for (int bi = 0; bi < 4; bi++) {
            PACK2(acc2[bi][0], xv[bi][0], xv[bi][1]);
            PACK2(acc2[bi][1], xv[bi][2], xv[bi][3]);
        }
        __syncthreads();

        // gates += h_prev @ Whh^T
#pragma unroll 2
        for (int k4 = 0; k4 < 64; ++k4) {
            float4 hv[4];
#pragma unroll
            for (int bi = 0; bi < 4; bi++)
                hv[bi] = *(const float4*)(sh_h + (bt + 32 * bi) * HST + k4 * 4);
#pragma unroll
            for (int i = 0; i < 4; i++) {
                ulonglong2 wv = *(const ulonglong2*)(wbase + (k4 * 4 + i) * 4);
#pragma unroll
                for (int bi = 0; bi < 4; bi++) {
                    float hs = (i == 0) ? hv[bi].x : (i == 1) ? hv[bi].y
                             : (i == 2) ? hv[bi].z : hv[bi].w;
                    ull hd;
                    DUP2(hd, hs);
                    FMA2(acc2[bi][0], hd, wv.x);
                    FMA2(acc2[bi][1], hd, wv.y);
                }
            }
        }

        // nonlinearity + state update + writes
        float* hdst = g_h + (size_t)(((t + 1) & 1) * 4 + rec) * BB * HH;
        float* odst = g_o + (size_t)s * LL * BB * DD + (size_t)l * BB * DD + dir * HH + j;
#pragma unroll
        for (int bi = 0; bi < 4; bi++) {
            int b = bt + 32 * bi;
            float pi, pf, pg, po;
            UNPACK2(pi, pf, acc2[bi][0]);
            UNPACK2(pg, po, acc2[bi][1]);
            float ig = sig_fast(pi);
            float fg = sig_fast(pf);
            float gg = tanh_fast(pg);
            float og = sig_fast(po);
            float c = fmaf(fg, c_st[bi], ig * gg);
            c_st[bi] = c;
            float h = og * tanh_fast(c);
            hdst[(size_t)b * HH + j] = h;
            odst[(size_t)b * DD] = h;
        }

        // global barrier (all 128 blocks co-resident at 1/SM)
        __syncthreads();   // all threads' stores issued before arrival
        if (tid == 0) {
            __threadfence();
            atomicAdd(&g_sync, 1u);
            unsigned target = 128u * (unsigned)(t + 1);
            while (*((volatile unsigned*)&g_sync) < target) { }
            __threadfence();
        }
        __syncthreads();
    }

    // self-reset for graph replays
    if (tid == 0) {
        unsigned old = atomicAdd(&g_done, 1u);
        if (old == 127u) {
            g_done = 0u;
            g_sync = 0u;
            __threadfence();
        }
    }
}

// ---------------- kernel 4: mp1 = max over time of o1 ----------------
__global__ void mp1_kernel() {
    int b = blockIdx.x;
    for (int d = threadIdx.x; d < DD; d += blockDim.x) {
        float m = -FLT_MAX;
#pragma unroll 8
        for (int l = 0; l < LL; l++)
            m = fmaxf(m, g_o[(size_t)l * BB * DD + b * DD + d]);
        g_mp1[b * DD + d] = m;
    }
}

// ---------------- kernel 5: attention + softmax (raw-reshape semantics) ----
__global__ void att_kernel() {
    __shared__ float smp[DD];
    __shared__ float sat[LL];
    int b = blockIdx.x, l = threadIdx.x;   // 64 threads
    const float* o2 = g_o + (size_t)LL * BB * DD;
    for (int d = l; d < DD; d += LL) smp[d] = g_mp1[b * DD + d];
    __syncthreads();
    float a = 0.0f;
    for (int d = 0; d < DD; d++)
        a = fmaf(smp[d], o2[(size_t)b * DD * LL + d * LL + l], a);
    sat[l] = a;
    __syncthreads();
    float mx = -FLT_MAX;
    for (int i = 0; i < LL; i++) mx = fmaxf(mx, sat[i]);
    float ssum = 0.0f;
    for (int i = 0; i < LL; i++) ssum += expf(sat[i] - mx);
    g_attsm[b * LL + l] = expf(a - mx) / ssum;
}

// ---------------- kernel 6: new_pool + sim (fused) ----------------
__global__ void sim_kernel(float* __restrict__ out) {
    __shared__ float sal[LL];
    __shared__ float red[256];
    int b = blockIdx.x, tid = threadIdx.x;
    if (tid < LL) sal[tid] = g_attsm[b * LL + tid];
    __syncthreads();
    const float* o2 = g_o + (size_t)LL * BB * DD;
    float local = 0.0f;
    for (int d = tid; d < DD; d += 256) {
        float np = 0.0f;
#pragma unroll 8
        for (int l = 0; l < LL; l++)
            np = fmaf(sal[l], o2[(size_t)b * LL * DD + l * DD + d], np);
        local += fabsf(g_mp1[b * DD + d] - np);
    }
    red[tid] = local;
    __syncthreads();
    for (int s2 = 128; s2 > 0; s2 >>= 1) {
        if (tid < s2) red[tid] += red[tid + s2];
        __syncthreads();
    }
    if (tid == 0) out[b] = expf(-red[0]);
}

// ---------------- kernel 7: commonWords + e1h/e2h ----------------
__global__ void e_kernel(const int* __restrict__ t1, const int* __restrict__ t2,
                         float* __restrict__ out) {
    __shared__ int s1[LL];
    __shared__ int spos[LL];
    __shared__ int smask[LL];
    __shared__ int shas;
    int b = blockIdx.x, tid = threadIdx.x;
    if (tid == 0) shas = 0;
    if (tid < LL) s1[tid] = t1[tid * BB + b];
    __syncthreads();
    if (tid < LL) {
        int tok2 = t2[tid * BB + b];
        int d = -1;
        for (int jj = 0; jj < LL; jj++)
            if (s1[jj] == tok2) d = jj;
        int m = (d > 1) && (tok2 > 0);
        smask[tid] = m;
        spos[tid] = min(max(d, 0), LL - 1);
        if (m) atomicOr(&shas, 1);
    }
    __syncthreads();
    int has = shas;
    const float* o1 = g_o;
    const float* o2 = g_o + (size_t)LL * BB * DD;
    for (int d = tid; d < DD; d += 256) {
        float m1 = -FLT_MAX, m2 = -FLT_MAX;
        for (int i = 0; i < LL; i++) {
            if (smask[i]) {
                m1 = fmaxf(m1, o1[(size_t)spos[i] * BB * DD + b * DD + d]);
                m2 = fmaxf(m2, o2[(size_t)i * BB * DD + b * DD + d]);
            }
        }
        out[128 + b * DD + d] = has ? m1 : 0.0f;
        out[128 + BB * DD + b * DD + d] = has ? m2 : 0.0f;
    }
}

// ---------------- launch ----------------
extern "C" void kernel_launch(void* const* d_in, const int* in_sizes, int n_in,
                              void* d_out, int out_size) {
    const int* t1 = (const int*)d_in[0];
    const int* t2 = (const int*)d_in[1];
    const float* emb = (const float*)d_in[2];
    const float* Wihf = (const float*)d_in[3];
    const float* Whhf = (const float*)d_in[4];
    const float* bihf = (const float*)d_in[5];
    const float* bhhf = (const float*)d_in[6];
    const float* Wihb = (const float*)d_in[7];
    const float* Whhb = (const float*)d_in[8];
    const float* bihb = (const float*)d_in[9];
    const float* bhhb = (const float*)d_in[10];
    float* out = (float*)d_out;

    zero_h_kernel<<<(2 * 4 * BB * HH + 255) / 256, 256>>>();
    gather_kernel<<<NROWS, 128>>>(t1, t2, emb);

    dim3 ggrid(128, 16);
    gemm_kernel<<<ggrid, 256>>>(Wihf, Wihb, bihf, bhhf, bihb, bhhb);

    const int lstm_smem = (8 * WST + 128 * HST) * 4;  // 166,016 B
    cudaFuncSetAttribute(lstm_kernel, cudaFuncAttributeMaxDynamicSharedMemorySize, lstm_smem);
    lstm_kernel<<<128, 256, lstm_smem>>>(Whhf, Whhb);

    mp1_kernel<<<BB, 128>>>();
    att_kernel<<<BB, LL>>>();
    sim_kernel<<<BB, 256>>>(out);
    e_kernel<<<BB, 256>>>(t1, t2, out);
}